// round 1
// baseline (speedup 1.0000x reference)
#include <cuda_runtime.h>
#include <math.h>

#define B_SZ   4096
#define IN_SZ  1024
#define HID_SZ 2048
#define OUT_SZ 512

// scratch: rate transposed [HID][BATCH] (m-contiguous rows)
__device__ float g_Rt[(size_t)HID_SZ * B_SZ];

__device__ __forceinline__ unsigned long long pack2(float x, float y) {
    unsigned long long r;
    asm("mov.b64 %0, {%1, %2};" : "=l"(r) : "f"(x), "f"(y));
    return r;
}
__device__ __forceinline__ void unpack2(unsigned long long p, float& x, float& y) {
    asm("mov.b64 {%0, %1}, %2;" : "=f"(x), "=f"(y) : "l"(p));
}
__device__ __forceinline__ void ffma2(unsigned long long& c, unsigned long long a, unsigned long long b) {
    asm("fma.rn.f32x2 %0, %1, %2, %0;" : "+l"(c) : "l"(a), "l"(b));
}

// GEMM1: Rt[n][m] = 0.35*sigmoid((6/7)*(sum_k psp[k][m]*W_h[n][k] + b_h[n]))
// A = psp [IN][B] (m contiguous), B = W_h [HID][IN] (k contiguous)
__global__ __launch_bounds__(256, 2)
void k_hidden(const float* __restrict__ A, const float* __restrict__ Bw,
              const float* __restrict__ bias)
{
    __shared__ float As[8][128];
    __shared__ float Bs[8][128];
    const int m0 = blockIdx.x * 128;
    const int n0 = blockIdx.y * 128;
    const int tid = threadIdx.x;
    const int tx = tid & 15;   // n group (8 cols)
    const int ty = tid >> 4;   // m group (8 rows)
    const int a_k = tid >> 5, a_m = (tid & 31) << 2;
    const int b_n = tid >> 1, b_k = (tid & 1) << 2;
    const float* Ap = A + (size_t)a_k * B_SZ + m0 + a_m;
    const float* Bp = Bw + (size_t)(n0 + b_n) * IN_SZ + b_k;

    unsigned long long c2[4][8];
#pragma unroll
    for (int i = 0; i < 4; i++)
#pragma unroll
        for (int j = 0; j < 8; j++) c2[i][j] = 0ull;

    for (int k0 = 0; k0 < IN_SZ; k0 += 8) {
        const float4 av = *(const float4*)(Ap + (size_t)k0 * B_SZ);
        const float4 bv = *(const float4*)(Bp + k0);
        *(float4*)&As[a_k][a_m] = av;
        Bs[b_k + 0][b_n] = bv.x;
        Bs[b_k + 1][b_n] = bv.y;
        Bs[b_k + 2][b_n] = bv.z;
        Bs[b_k + 3][b_n] = bv.w;
        __syncthreads();
#pragma unroll
        for (int k = 0; k < 8; k++) {
            const ulonglong2 ua0 = *(const ulonglong2*)&As[k][ty * 8];
            const ulonglong2 ua1 = *(const ulonglong2*)&As[k][ty * 8 + 4];
            const float4 bv0 = *(const float4*)&Bs[k][tx * 8];
            const float4 bv1 = *(const float4*)&Bs[k][tx * 8 + 4];
            unsigned long long a2[4];
            a2[0] = ua0.x; a2[1] = ua0.y; a2[2] = ua1.x; a2[3] = ua1.y;
            unsigned long long bb[8];
            bb[0] = pack2(bv0.x, bv0.x); bb[1] = pack2(bv0.y, bv0.y);
            bb[2] = pack2(bv0.z, bv0.z); bb[3] = pack2(bv0.w, bv0.w);
            bb[4] = pack2(bv1.x, bv1.x); bb[5] = pack2(bv1.y, bv1.y);
            bb[6] = pack2(bv1.z, bv1.z); bb[7] = pack2(bv1.w, bv1.w);
#pragma unroll
            for (int i = 0; i < 4; i++)
#pragma unroll
                for (int j = 0; j < 8; j++) ffma2(c2[i][j], a2[i], bb[j]);
        }
        __syncthreads();
    }

    const float s = 6.0f / 7.0f;
    const float4 bias0 = *(const float4*)&bias[n0 + tx * 8];
    const float4 bias1 = *(const float4*)&bias[n0 + tx * 8 + 4];
    const float bvals[8] = {bias0.x, bias0.y, bias0.z, bias0.w,
                            bias1.x, bias1.y, bias1.z, bias1.w};
#pragma unroll
    for (int j = 0; j < 8; j++) {
        const int n = n0 + tx * 8 + j;
        const float bb = bvals[j];
        float r[8];
#pragma unroll
        for (int i = 0; i < 4; i++) {
            float x, y;
            unpack2(c2[i][j], x, y);
            const float vx = s * (x + bb);
            const float vy = s * (y + bb);
            r[2 * i]     = 0.35f / (1.0f + expf(-vx));
            r[2 * i + 1] = 0.35f / (1.0f + expf(-vy));
        }
        float* dst = g_Rt + (size_t)n * B_SZ + m0 + ty * 8;
        *(float4*)dst       = *(const float4*)&r[0];
        *(float4*)(dst + 4) = *(const float4*)&r[4];
    }
}

// GEMM2: out[m][n] = 0.35*sigmoid(0.75*(sum_h Rt[h][m]*W_o[n][h]) + 0.75*b_o[n] + 0.125*label[m][n])
// A = g_Rt [HID][B] (m contiguous), B = W_o [OUT][HID] (k contiguous)
__global__ __launch_bounds__(256, 2)
void k_out(const float* __restrict__ Bw, const float* __restrict__ bias,
           const float* __restrict__ label, float* __restrict__ out)
{
    __shared__ float As[8][128];
    __shared__ float Bs[8][64];
    const int m0 = blockIdx.x * 128;
    const int n0 = blockIdx.y * 64;
    const int tid = threadIdx.x;
    const int tx = tid & 15;   // n group (4 cols)
    const int ty = tid >> 4;   // m group (8 rows)
    const int a_k = tid >> 5, a_m = (tid & 31) << 2;
    const int b_n = tid >> 2, b_k = (tid & 3) << 1;
    const float* Ap = g_Rt + (size_t)a_k * B_SZ + m0 + a_m;
    const float* Bp = Bw + (size_t)(n0 + b_n) * HID_SZ + b_k;

    unsigned long long c2[4][4];
#pragma unroll
    for (int i = 0; i < 4; i++)
#pragma unroll
        for (int j = 0; j < 4; j++) c2[i][j] = 0ull;

    for (int k0 = 0; k0 < HID_SZ; k0 += 8) {
        const float4 av = *(const float4*)(Ap + (size_t)k0 * B_SZ);
        const float2 bv = *(const float2*)(Bp + k0);
        *(float4*)&As[a_k][a_m] = av;
        Bs[b_k + 0][b_n] = bv.x;
        Bs[b_k + 1][b_n] = bv.y;
        __syncthreads();
#pragma unroll
        for (int k = 0; k < 8; k++) {
            const ulonglong2 ua0 = *(const ulonglong2*)&As[k][ty * 8];
            const ulonglong2 ua1 = *(const ulonglong2*)&As[k][ty * 8 + 4];
            const float4 bv0 = *(const float4*)&Bs[k][tx * 4];
            unsigned long long a2[4];
            a2[0] = ua0.x; a2[1] = ua0.y; a2[2] = ua1.x; a2[3] = ua1.y;
            unsigned long long bb[4];
            bb[0] = pack2(bv0.x, bv0.x); bb[1] = pack2(bv0.y, bv0.y);
            bb[2] = pack2(bv0.z, bv0.z); bb[3] = pack2(bv0.w, bv0.w);
#pragma unroll
            for (int i = 0; i < 4; i++)
#pragma unroll
                for (int j = 0; j < 4; j++) ffma2(c2[i][j], a2[i], bb[j]);
        }
        __syncthreads();
    }

    // unpack accumulators: c[m_local][n_local]
    float c[8][4];
#pragma unroll
    for (int i = 0; i < 4; i++)
#pragma unroll
        for (int j = 0; j < 4; j++)
            unpack2(c2[i][j], c[2 * i][j], c[2 * i + 1][j]);

    const float4 bo = *(const float4*)&bias[n0 + tx * 4];
    const float bo75[4] = {0.75f * bo.x, 0.75f * bo.y, 0.75f * bo.z, 0.75f * bo.w};
#pragma unroll
    for (int i = 0; i < 8; i++) {
        const int m = m0 + ty * 8 + i;
        const float4 lb = *(const float4*)&label[(size_t)m * OUT_SZ + n0 + tx * 4];
        float v[4];
        v[0] = 0.75f * c[i][0] + bo75[0] + 0.125f * lb.x;
        v[1] = 0.75f * c[i][1] + bo75[1] + 0.125f * lb.y;
        v[2] = 0.75f * c[i][2] + bo75[2] + 0.125f * lb.z;
        v[3] = 0.75f * c[i][3] + bo75[3] + 0.125f * lb.w;
        float4 o;
        o.x = 0.35f / (1.0f + expf(-v[0]));
        o.y = 0.35f / (1.0f + expf(-v[1]));
        o.z = 0.35f / (1.0f + expf(-v[2]));
        o.w = 0.35f / (1.0f + expf(-v[3]));
        *(float4*)&out[(size_t)m * OUT_SZ + n0 + tx * 4] = o;
    }
}

extern "C" void kernel_launch(void* const* d_in, const int* in_sizes, int n_in,
                              void* d_out, int out_size) {
    const float* psp   = (const float*)d_in[0];  // [1024, 4096]
    const float* label = (const float*)d_in[1];  // [4096, 512]
    const float* W_h   = (const float*)d_in[2];  // [2048, 1024]
    const float* b_h   = (const float*)d_in[3];  // [2048]
    const float* W_o   = (const float*)d_in[4];  // [512, 2048]
    const float* b_o   = (const float*)d_in[5];  // [512]
    float* out = (float*)d_out;                  // [4096, 512]

    k_hidden<<<dim3(B_SZ / 128, HID_SZ / 128), 256>>>(psp, W_h, b_h);
    k_out<<<dim3(B_SZ / 128, OUT_SZ / 64), 256>>>(W_o, b_o, label, out);
}